// round 6
// baseline (speedup 1.0000x reference)
#include <cuda_runtime.h>
#include <cuda_fp16.h>

// Trilinear interpolation, fp16 channel-last scratch + 4-lane pair gather,
// 2 points per thread for doubled memory-level parallelism.
//   input  d_in[0]: float32 [16, 128, 128, 128]  (C, z, y, x)
//   coords d_in[1]: float32 [1000000, 3] in [-1, 1]
//   out    d_out  : float32 [16, 1000000]

#define GS        128
#define NCH       16
#define NSPATIAL  (GS * GS * GS)
#define PAD_CELLS (GS * GS + GS + 1)   // +1 plane/row/cell for unclamped +1 corners

// fp16 scratch, zero-initialized (pad region must read as 0.0)
__device__ __half g_trans[(size_t)NCH * (NSPATIAL + PAD_CELLS)];

__device__ __forceinline__ unsigned long long make_evict_last_policy() {
    unsigned long long pol;
    asm volatile("createpolicy.fractional.L2::evict_last.b64 %0, 1.0;" : "=l"(pol));
    return pol;
}

__device__ __forceinline__ uint4 ldg_hint(const void* p, unsigned long long pol) {
    uint4 v;
    asm volatile("ld.global.L2::cache_hint.v4.u32 {%0,%1,%2,%3}, [%4], %5;"
                 : "=r"(v.x), "=r"(v.y), "=r"(v.z), "=r"(v.w)
                 : "l"(p), "l"(pol));
    return v;
}

__device__ __forceinline__ void stg_hint(void* p, uint4 v, unsigned long long pol) {
    asm volatile("st.global.L2::cache_hint.v4.u32 [%0], {%1,%2,%3,%4}, %5;"
                 :: "l"(p), "r"(v.x), "r"(v.y), "r"(v.z), "r"(v.w), "l"(pol)
                 : "memory");
}

__global__ void __launch_bounds__(256) transpose_kernel(const float* __restrict__ in) {
    int idx = blockIdx.x * blockDim.x + threadIdx.x;
    if (idx >= NSPATIAL) return;
    unsigned long long pol = make_evict_last_policy();
    __half v[NCH];
#pragma unroll
    for (int c = 0; c < NCH; c++) {
        v[c] = __float2half_rn(__ldcs(in + (size_t)c * NSPATIAL + idx)); // streaming
    }
    uint4* dst = reinterpret_cast<uint4*>(g_trans + (size_t)idx * NCH);
    const uint4* src = reinterpret_cast<const uint4*>(v);
    stg_hint(dst + 0, src[0], pol);   // grid born L2-resident, retain priority
    stg_hint(dst + 1, src[1], pol);
}

// Compute per-point setup: cell base pointer + this lane's corner weights.
struct PointCtx {
    const char* base;   // &cell(z0,y0,x0) + lane*16
    float w[4];         // weight for each (z,y) corner combo, incl. lane's x weight
};

__device__ __forceinline__ PointCtx setup_point(const float* __restrict__ coords,
                                                int n, int lane) {
    float c0 = __ldcs(coords + 3 * n + 0);
    float c1 = __ldcs(coords + 3 * n + 1);
    float c2 = __ldcs(coords + 3 * n + 2);
    float f0 = fminf(fmaxf(fmaf(c0, 63.5f, 63.5f), 0.0f), 127.0f);
    float f1 = fminf(fmaxf(fmaf(c1, 63.5f, 63.5f), 0.0f), 127.0f);
    float f2 = fminf(fmaxf(fmaf(c2, 63.5f, 63.5f), 0.0f), 127.0f);

    float fl0 = floorf(f0), fl1 = floorf(f1), fl2 = floorf(f2);
    float r0 = f0 - fl0, r1 = f1 - fl1, r2 = f2 - fl2;

    int cell00 = (((int)fl0 * GS + (int)fl1) * GS + (int)fl2);

    float wxl = (lane < 2) ? (1.0f - r2) : r2;
    PointCtx p;
    p.base = reinterpret_cast<const char*>(g_trans) + (size_t)cell00 * 32 + lane * 16;
    p.w[0] = (1.0f - r0) * (1.0f - r1) * wxl;   // z0 y0
    p.w[1] = (1.0f - r0) * r1 * wxl;            // z0 y1
    p.w[2] = r0 * (1.0f - r1) * wxl;            // z1 y0
    p.w[3] = r0 * r1 * wxl;                     // z1 y1
    return p;
}

__device__ __forceinline__ void fma_corner(float* acc, uint4 raw, float w) {
    float2 v0 = __half22float2(*reinterpret_cast<__half2*>(&raw.x));
    float2 v1 = __half22float2(*reinterpret_cast<__half2*>(&raw.y));
    float2 v2 = __half22float2(*reinterpret_cast<__half2*>(&raw.z));
    float2 v3 = __half22float2(*reinterpret_cast<__half2*>(&raw.w));
    acc[0] = fmaf(w, v0.x, acc[0]);
    acc[1] = fmaf(w, v0.y, acc[1]);
    acc[2] = fmaf(w, v1.x, acc[2]);
    acc[3] = fmaf(w, v1.y, acc[3]);
    acc[4] = fmaf(w, v2.x, acc[4]);
    acc[5] = fmaf(w, v2.y, acc[5]);
    acc[6] = fmaf(w, v3.x, acc[6]);
    acc[7] = fmaf(w, v3.y, acc[7]);
}

// byte offsets of the 4 (z,y) corner combos in the channel-last layout
__device__ __forceinline__ size_t corner_off(int k) {
    // k: 0=(z0,y0) 1=(z0,y1) 2=(z1,y0) 3=(z1,y1)
    return ((size_t)(k >> 1) * (GS * GS) + (size_t)(k & 1) * GS) * 32;
}

__global__ void __launch_bounds__(256) gather_kernel(const float* __restrict__ coords,
                                                     float* __restrict__ out,
                                                     int N, int halfN) {
    int t    = blockIdx.x * blockDim.x + threadIdx.x;
    int p    = t >> 2;        // point-pair index
    int lane = t & 3;         // 0: x0/ch0-7  1: x0/ch8-15  2: x1/ch0-7  3: x1/ch8-15
    if (p >= halfN) return;

    unsigned long long pol = make_evict_last_policy();

    int n0 = p;
    int n1 = p + halfN;
    bool has2 = (n1 < N);

    PointCtx p0 = setup_point(coords, n0, lane);
    PointCtx p1 = setup_point(coords, has2 ? n1 : n0, lane);

    // batch all 8 loads before consuming -> MLP 8 per thread
    uint4 raw0[4], raw1[4];
#pragma unroll
    for (int k = 0; k < 4; k++) raw0[k] = ldg_hint(p0.base + corner_off(k), pol);
#pragma unroll
    for (int k = 0; k < 4; k++) raw1[k] = ldg_hint(p1.base + corner_off(k), pol);

    float acc0[8], acc1[8];
#pragma unroll
    for (int k = 0; k < 8; k++) { acc0[k] = 0.0f; acc1[k] = 0.0f; }

#pragma unroll
    for (int k = 0; k < 4; k++) fma_corner(acc0, raw0[k], p0.w[k]);
#pragma unroll
    for (int k = 0; k < 4; k++) fma_corner(acc1, raw1[k], p1.w[k]);

    // combine x0/x1 partials: partner lane is lane^2 (same point, always active)
    unsigned mask = __activemask();
#pragma unroll
    for (int k = 0; k < 8; k++) {
        acc0[k] += __shfl_xor_sync(mask, acc0[k], 2);
        acc1[k] += __shfl_xor_sync(mask, acc1[k], 2);
    }

    // lanes 0,2 hold final ch0-7; lanes 1,3 hold final ch8-15.
    //   lane0: ch0-3  lane2: ch4-7  lane1: ch8-11  lane3: ch12-15
    int sel    = lane >> 1;
    int chbase = (lane & 1) * 8 + sel * 4;
#pragma unroll
    for (int j = 0; j < 4; j++) {
        __stcs(out + (size_t)(chbase + j) * N + n0, acc0[sel * 4 + j]);
    }
    if (has2) {
#pragma unroll
        for (int j = 0; j < 4; j++) {
            __stcs(out + (size_t)(chbase + j) * N + n1, acc1[sel * 4 + j]);
        }
    }
}

extern "C" void kernel_launch(void* const* d_in, const int* in_sizes, int n_in,
                              void* d_out, int out_size) {
    const float* input  = (const float*)d_in[0];
    const float* coords = (const float*)d_in[1];
    float* out = (float*)d_out;
    int N = in_sizes[1] / 3;
    int halfN = (N + 1) / 2;

    transpose_kernel<<<(NSPATIAL + 255) / 256, 256>>>(input);

    long long threads = 4LL * halfN;
    int blocks = (int)((threads + 255) / 256);
    gather_kernel<<<blocks, 256>>>(coords, out, N, halfN);
}

// round 7
// speedup vs baseline: 1.1865x; 1.1865x over previous
#include <cuda_runtime.h>
#include <cuda_fp16.h>

// Trilinear interpolation: fp16 channel-last scratch + 2-lane 256-bit gather.
//   input  d_in[0]: float32 [16, 128, 128, 128]  (C, z, y, x)
//   coords d_in[1]: float32 [1000000, 3] in [-1, 1]
//   out    d_out  : float32 [16, 1000000]
//
// 1) transpose: [C][z][y][x] f32 -> [z][y][x][C] f16 (64 MB, ~L2-resident).
// 2) gather: 2 lanes per point. Each 32 B cell (16 ch fp16) is loaded with a
//    single ld.global.v8.u32: lane0 takes x-corner x0, lane1 takes x0+1, per
//    (z,y) combo -> 4 loads/lane. x-partials combined with 8 shfl+add/lane.
//    Out-of-range "+1" corners carry weight 0 and land in a zeroed pad.

#define GS        128
#define NCH       16
#define NSPATIAL  (GS * GS * GS)
#define PAD_CELLS (GS * GS + GS + 1)   // +1 plane/row/cell for unclamped +1 corners

// fp16 scratch, zero-initialized; 32B-aligned cells need an aligned base
__device__ __align__(128) __half g_trans[(size_t)NCH * (NSPATIAL + PAD_CELLS)];

struct U8 { unsigned r0, r1, r2, r3, r4, r5, r6, r7; };

__device__ __forceinline__ U8 ldg256_evict_last(const void* p) {
    U8 v;
    asm volatile("ld.global.L2::evict_last.v8.u32 {%0,%1,%2,%3,%4,%5,%6,%7}, [%8];"
                 : "=r"(v.r0), "=r"(v.r1), "=r"(v.r2), "=r"(v.r3),
                   "=r"(v.r4), "=r"(v.r5), "=r"(v.r6), "=r"(v.r7)
                 : "l"(p));
    return v;
}

__device__ __forceinline__ void stg256_evict_last(void* p, unsigned long long a,
                                                  unsigned long long b,
                                                  unsigned long long c,
                                                  unsigned long long d) {
    asm volatile("st.global.L2::evict_last.v4.u64 [%0], {%1,%2,%3,%4};"
                 :: "l"(p), "l"(a), "l"(b), "l"(c), "l"(d) : "memory");
}

__global__ void __launch_bounds__(256) transpose_kernel(const float* __restrict__ in) {
    int idx = blockIdx.x * blockDim.x + threadIdx.x;
    if (idx >= NSPATIAL) return;
    __half2 v[NCH / 2];
#pragma unroll
    for (int c = 0; c < NCH; c += 2) {
        float a = __ldcs(in + (size_t)c * NSPATIAL + idx);        // streaming reads
        float b = __ldcs(in + (size_t)(c + 1) * NSPATIAL + idx);
        v[c / 2] = __floats2half2_rn(a, b);
    }
    const unsigned long long* s = reinterpret_cast<const unsigned long long*>(v);
    // grid born L2-resident with retention priority (single 32B store)
    stg256_evict_last(g_trans + (size_t)idx * NCH, s[0], s[1], s[2], s[3]);
}

__global__ void __launch_bounds__(256) gather_kernel(const float* __restrict__ coords,
                                                     float* __restrict__ out,
                                                     int N) {
    int t    = blockIdx.x * blockDim.x + threadIdx.x;
    int n    = t >> 1;        // point index
    int lane = t & 1;         // x-corner this thread owns (x0 or x0+1)
    if (n >= N) return;

    float c0 = __ldcs(coords + 3 * n + 0);
    float c1 = __ldcs(coords + 3 * n + 1);
    float c2 = __ldcs(coords + 3 * n + 2);
    // map [-1,1] -> [0,127], clamp in fp: +1 corners may land in the zero pad
    // but always carry weight 0 there.
    float f0 = fminf(fmaxf(fmaf(c0, 63.5f, 63.5f), 0.0f), 127.0f);
    float f1 = fminf(fmaxf(fmaf(c1, 63.5f, 63.5f), 0.0f), 127.0f);
    float f2 = fminf(fmaxf(fmaf(c2, 63.5f, 63.5f), 0.0f), 127.0f);

    float fl0 = floorf(f0), fl1 = floorf(f1), fl2 = floorf(f2);
    float r0 = f0 - fl0, r1 = f1 - fl1, r2 = f2 - fl2;

    int cell00 = (((int)fl0 * GS + (int)fl1) * GS + (int)fl2);

    float wxl = lane ? r2 : (1.0f - r2);          // this lane's x weight
    float wzy[4];
    wzy[0] = (1.0f - r0) * (1.0f - r1) * wxl;     // z0 y0
    wzy[1] = (1.0f - r0) * r1 * wxl;              // z0 y1
    wzy[2] = r0 * (1.0f - r1) * wxl;              // z1 y0
    wzy[3] = r0 * r1 * wxl;                       // z1 y1

    // lane's cell: x0 (+0) or x0+1 (+32 B)
    const char* base = reinterpret_cast<const char*>(g_trans)
                     + (size_t)cell00 * 32 + (unsigned)lane * 32;

    float acc[16];
#pragma unroll
    for (int k = 0; k < 16; k++) acc[k] = 0.0f;

#pragma unroll
    for (int k = 0; k < 4; k++) {
        float w = wzy[k];
        U8 raw = ldg256_evict_last(
            base + ((size_t)(k >> 1) * (GS * GS) + (size_t)(k & 1) * GS) * 32);
        const unsigned* r = &raw.r0;
#pragma unroll
        for (int j = 0; j < 8; j++) {
            float2 v = __half22float2(*reinterpret_cast<const __half2*>(&r[j]));
            acc[2 * j + 0] = fmaf(w, v.x, acc[2 * j + 0]);
            acc[2 * j + 1] = fmaf(w, v.y, acc[2 * j + 1]);
        }
    }

    // combine x0/x1 partials. lane0 stores ch0-7, lane1 stores ch8-15;
    // each lane sends the half its partner stores, receives its own half.
    unsigned mask = __activemask();
    float fin[8];
#pragma unroll
    for (int j = 0; j < 8; j++) {
        float send = lane ? acc[j] : acc[8 + j];
        float keep = lane ? acc[8 + j] : acc[j];
        fin[j] = keep + __shfl_xor_sync(mask, send, 1);
    }

    int chbase = lane * 8;
    size_t nn = (size_t)n;
#pragma unroll
    for (int j = 0; j < 8; j++) {
        __stcs(out + (size_t)(chbase + j) * N + nn, fin[j]);
    }
}

extern "C" void kernel_launch(void* const* d_in, const int* in_sizes, int n_in,
                              void* d_out, int out_size) {
    const float* input  = (const float*)d_in[0];
    const float* coords = (const float*)d_in[1];
    float* out = (float*)d_out;
    int N = in_sizes[1] / 3;

    transpose_kernel<<<(NSPATIAL + 255) / 256, 256>>>(input);

    long long threads = 2LL * N;
    int blocks = (int)((threads + 255) / 256);
    gather_kernel<<<blocks, 256>>>(coords, out, N);
}